// round 12
// baseline (speedup 1.0000x reference)
#include <cuda_runtime.h>
#include <cuda_fp16.h>
#include <cstdint>

// ============================================================================
// SeparableAttention — round 11: N=128 per block (two h-columns), fp16 2-term
// split W via per-fragment LDG tables, B tile resident in smem.
//   grid 1024 = 32 b x 32 h-pairs; 256 thr; 1 CTA/SM (144KB smem).
//   warp tile: M=32, N=128 -> wf/MMA 0.75 (was 1.0) -> MMA-bound.
// ============================================================================

#define XROW 136                            // halves per row (272 B, pad 8)
#define OFF_XH   0                          // Xh fp16 [256][136] = 69632 B
#define OFF_SCR  69632                      // Xl fp16 tile / Wks fp32 alias
#define OFF_TAIL 139264
#define SMEM_BYTES (OFF_TAIL + 8192)        // 147456 B

// W fragments: [gemm][half][ks][mtile][lane]
__device__ uint4 sc_WF[2][2][16][16][32];   // 512 KB
#define HOFF (16 * 16 * 32)

// ---------------------------- helpers ---------------------------------------
__device__ __forceinline__ uint32_t smem_u32(const void* p) {
    uint32_t a;
    asm("{ .reg .u64 t; cvta.to.shared.u64 t, %1; cvt.u32.u64 %0, t; }"
        : "=r"(a) : "l"(p));
    return a;
}
__device__ __forceinline__ uint32_t pack2h(float a, float b) {
    __half2 t = __floats2half2_rn(a, b);
    return *reinterpret_cast<uint32_t*>(&t);
}
__device__ __forceinline__ float h_hi(float v) {
    return __half2float(__float2half_rn(v));
}

#define LDM4T(r0, r1, r2, r3, a) \
    asm volatile("ldmatrix.sync.aligned.m8n8.x4.trans.shared.b16 {%0,%1,%2,%3}, [%4];" \
        : "=r"(r0), "=r"(r1), "=r"(r2), "=r"(r3) : "r"(a))
#define MMA4(d, a, b) \
    asm volatile("mma.sync.aligned.m16n8k16.row.col.f32.f16.f16.f32 " \
        "{%0,%1,%2,%3}, {%4,%5,%6,%7}, {%8,%9}, {%0,%1,%2,%3};" \
        : "+f"((d)[0]), "+f"((d)[1]), "+f"((d)[2]), "+f"((d)[3]) \
        : "r"((a).x), "r"((a).y), "r"((a).z), "r"((a).w), \
          "r"((b)[0]), "r"((b)[1]))

// ============================================================================
// prep: per-fragment fp16 hi/lo W tables (mma.m16n8k16 A layout).
// ============================================================================
__global__ void prep_kernel(const float* __restrict__ Wqkv,
                            const float* __restrict__ Wout)
{
    int idx = blockIdx.x * 256 + threadIdx.x;
    int lane  = idx & 31;
    int mtile = (idx >> 5) & 15;
    int ks    = (idx >> 9) & 15;
    int gemm  = idx >> 13;
    const float* W = gemm ? Wout : (Wqkv + (size_t)257 * 256);

    int g = lane >> 2, t = lane & 3;
    int r0 = mtile * 16 + g, r1 = r0 + 8;
    int c0 = ks * 16 + 2 * t, c2 = c0 + 8;

    float w00 = W[r0 * 256 + c0], w01 = W[r0 * 256 + c0 + 1];
    float w10 = W[r1 * 256 + c0], w11 = W[r1 * 256 + c0 + 1];
    float w02 = W[r0 * 256 + c2], w03 = W[r0 * 256 + c2 + 1];
    float w12 = W[r1 * 256 + c2], w13 = W[r1 * 256 + c2 + 1];

    float h00 = h_hi(w00), h01 = h_hi(w01), h10 = h_hi(w10), h11 = h_hi(w11);
    float h02 = h_hi(w02), h03 = h_hi(w03), h12 = h_hi(w12), h13 = h_hi(w13);

    uint4 hi, lo;
    hi.x = pack2h(h00, h01); hi.y = pack2h(h10, h11);
    hi.z = pack2h(h02, h03); hi.w = pack2h(h12, h13);
    lo.x = pack2h(w00 - h00, w01 - h01); lo.y = pack2h(w10 - h10, w11 - h11);
    lo.z = pack2h(w02 - h02, w03 - h03); lo.w = pack2h(w12 - h12, w13 - h13);

    sc_WF[gemm][0][ks][mtile][lane] = hi;
    sc_WF[gemm][1][ks][mtile][lane] = lo;
}

// ============================================================================
// One 256x128x256 GEMM: A via LDG.128 fragment tables (double-buffered regs),
// B = Xh smem tile [256][136] via ldmatrix.trans. No barriers inside.
// Warp tile M=32 x N=128; acc[2][16][4].
// ============================================================================
__device__ __forceinline__ void gemm_main(const uint4* __restrict__ WF,
                                          uint32_t smb,
                                          float acc[2][16][4], int tid)
{
    const int lane = tid & 31, wid = tid >> 5;
    const int lrow = (lane & 7) + ((lane >> 3) & 1) * 8;
    const int lcol = (lane >> 4) * 8;

    uint4 bh[2][2], bl[2][2];
    #pragma unroll
    for (int mf = 0; mf < 2; mf++) {
        int off = (wid * 2 + mf) * 32 + lane;
        bh[0][mf] = __ldg(WF + off);
        bl[0][mf] = __ldg(WF + HOFF + off);
    }

    #pragma unroll
    for (int ks = 0; ks < 16; ks++) {
        const int p = ks & 1;
        if (ks < 15) {
            #pragma unroll
            for (int mf = 0; mf < 2; mf++) {
                int off = ((ks + 1) * 16 + wid * 2 + mf) * 32 + lane;
                bh[1 - p][mf] = __ldg(WF + off);
                bl[1 - p][mf] = __ldg(WF + HOFF + off);
            }
        }
        uint32_t Bh[16][2];
        const uint32_t rbase = smb + OFF_XH + (uint32_t)(ks * 16 + lrow) * (XROW * 2);
        #pragma unroll
        for (int nn = 0; nn < 8; nn++) {
            uint32_t t0, t1, t2, t3;
            LDM4T(t0, t1, t2, t3, rbase + (nn * 16 + lcol) * 2);
            Bh[2 * nn][0] = t0;     Bh[2 * nn][1] = t1;
            Bh[2 * nn + 1][0] = t2; Bh[2 * nn + 1][1] = t3;
        }
        // hi term sweep (chain distance 32 per acc), then lo term sweep
        #pragma unroll
        for (int nf = 0; nf < 16; nf++) {
            MMA4(acc[0][nf], bh[p][0], Bh[nf]);
            MMA4(acc[1][nf], bh[p][1], Bh[nf]);
        }
        #pragma unroll
        for (int nf = 0; nf < 16; nf++) {
            MMA4(acc[0][nf], bl[p][0], Bh[nf]);
            MMA4(acc[1][nf], bl[p][1], Bh[nf]);
        }
    }
}

// ============================================================================
__global__ __launch_bounds__(256, 1)
void sepattn_tc(const float* __restrict__ x,
                const float* __restrict__ Wqkv,
                const float* __restrict__ bqkv,
                const float* __restrict__ bout,
                float* __restrict__ out)
{
    extern __shared__ char smc[];
    float* tail = (float*)(smc + OFF_TAIL);
    float* cv_s = tail;                        // 512 (h0, h1)
    float* q_s  = tail + 512;                  // 128
    float* s_s  = tail + 640;                  // 128
    float* xs_s = tail + 768;                  // 512 (h0, h1)
    float* Wq_s = tail + 1280;                 // 256
    float* qp   = tail + 1536;                 // 256
    float* red  = tail + 1792;                 // 8
    float* Wks  = (float*)(smc + OFF_SCR);     // cv staging alias over Xl
    const uint32_t smb = smem_u32(smc);

    const int tid = threadIdx.x;
    const int lane = tid & 31, wid = tid >> 5;
    const int b  = blockIdx.x >> 5;
    const int hp = blockIdx.x & 31;            // h-pair: cols [hp*128, +128)

    // -------- phase 0: load X [256 c][128 w], split Xh + Xl fp16 ------------
    const float2* x2 = (const float2*)(x + (size_t)b * 1048576);
    #pragma unroll
    for (int k = 0; k < 64; k++) {
        int idx = tid + k * 256;               // 16384 float2
        int w2 = idx & 63, c = idx >> 6;
        float2 v = __ldg(&x2[c * 2048 + hp * 64 + w2]);
        float h0 = h_hi(v.x), h1 = h_hi(v.y);
        uint32_t off = ((uint32_t)c * XROW + 2 * w2) * 2;
        *(uint32_t*)(smc + OFF_XH + off) = pack2h(h0, h1);
        *(uint32_t*)(smc + OFF_SCR + off) = pack2h(v.x - h0, v.y - h1);
    }
    if (tid < 64) {
        float4 v = __ldg(&((const float4*)Wqkv)[tid]);
        *(float4*)&Wq_s[4 * tid] = v;
    }
    __syncthreads();

    // -------- phase 1: q (128 w), 2x softmax, 2x xs, 2x cv ------------------
    {
        int w = tid & 127, part = tid >> 7;
        const __half* XH = (const __half*)(smc + OFF_XH);
        const __half* XL = (const __half*)(smc + OFF_SCR);
        float a = 0.f;
        #pragma unroll 8
        for (int c = part * 128; c < part * 128 + 128; c++)
            a = fmaf(Wq_s[c],
                     __half2float(XH[c * XROW + w]) + __half2float(XL[c * XROW + w]),
                     a);
        qp[part * 128 + w] = a;
    }
    __syncthreads();
    if (tid < 128) q_s[tid] = qp[tid] + qp[128 + tid] + __ldg(&bqkv[0]);
    __syncthreads();
    if (tid < 64) {                            // warp0 -> h0 max, warp1 -> h1
        int hh = tid >> 5, l = tid & 31;
        float m = fmaxf(q_s[hh * 64 + l], q_s[hh * 64 + 32 + l]);
        #pragma unroll
        for (int o = 16; o > 0; o >>= 1)
            m = fmaxf(m, __shfl_xor_sync(0xffffffffu, m, o));
        if (l == 0) red[hh] = m;
    }
    __syncthreads();
    if (tid < 128) q_s[tid] = __expf(q_s[tid] - red[tid >> 6]);
    __syncthreads();
    if (tid < 64) {
        int hh = tid >> 5, l = tid & 31;
        float s = q_s[hh * 64 + l] + q_s[hh * 64 + 32 + l];
        #pragma unroll
        for (int o = 16; o > 0; o >>= 1) s += __shfl_xor_sync(0xffffffffu, s, o);
        if (l == 0) red[2 + hh] = 1.0f / s;
    }
    __syncthreads();
    if (tid < 128) s_s[tid] = q_s[tid] * red[2 + (tid >> 6)];
    __syncthreads();

    {   // xs0/xs1[c] = sum_w (Xh+Xl)[c,w] s[w]   (c = tid)
        const __half2* XH2 = (const __half2*)(smc + OFF_XH);
        const __half2* XL2 = (const __half2*)(smc + OFF_SCR);
        float a0 = 0.f, a1 = 0.f;
        #pragma unroll 8
        for (int j = 0; j < 32; j++) {
            int jj = (j + tid) & 31;           // 5c+j bank walk: conflict-free
            float2 hf = __half22float2(XH2[tid * (XROW / 2) + jj]);
            float2 lf = __half22float2(XL2[tid * (XROW / 2) + jj]);
            a0 = fmaf(hf.x + lf.x, s_s[2 * jj], a0);
            a0 = fmaf(hf.y + lf.y, s_s[2 * jj + 1], a0);
            hf = __half22float2(XH2[tid * (XROW / 2) + 32 + jj]);
            lf = __half22float2(XL2[tid * (XROW / 2) + 32 + jj]);
            a1 = fmaf(hf.x + lf.x, s_s[64 + 2 * jj], a1);
            a1 = fmaf(hf.y + lf.y, s_s[64 + 2 * jj + 1], a1);
        }
        xs_s[tid] = a0;
        xs_s[256 + tid] = a1;
    }

    // cv{0,1}[c] = Wk[c,:].xs{0,1} + bk[c]   (Xl dead -> Wks staging)
    float cv0 = __ldg(&bqkv[1 + tid]), cv1 = cv0;
    const float4* W4full = (const float4*)Wqkv;
    for (int ec = 0; ec < 8; ec++) {
        __syncthreads();
        #pragma unroll
        for (int i = 0; i < 8; i++) {
            int idx = tid + i * 256;
            int r = idx >> 3, q = idx & 7;
            float4 v = __ldg(&W4full[(size_t)(1 + r) * 64 + ec * 8 + q]);
            *(float4*)&Wks[r * 36 + q * 4] = v;
        }
        __syncthreads();
        #pragma unroll 8
        for (int e = 0; e < 32; e++) {
            int er = (e + tid) & 31;
            float w = Wks[tid * 36 + er];
            cv0 = fmaf(w, xs_s[ec * 32 + er], cv0);
            cv1 = fmaf(w, xs_s[256 + ec * 32 + er], cv1);
        }
    }
    cv_s[tid] = cv0;
    cv_s[256 + tid] = cv1;
    // visibility covered by post-GEMM1 __syncthreads

    float acc[2][16][4];
    #pragma unroll
    for (int i = 0; i < 2; i++)
        #pragma unroll
        for (int j = 0; j < 16; j++)
            #pragma unroll
            for (int k = 0; k < 4; k++) acc[i][j][k] = 0.f;

    // ================= GEMM1: V = Wv . X =================
    gemm_main(&sc_WF[0][0][0][0][0], smb, acc, tid);

    __syncthreads();            // B reads done before overwriting Xh with G
    {   // epi1: g = relu(v+bv)*cv{h} -> Xh
        const int rb = wid * 32 + (lane >> 2);
        const int cb = 2 * (lane & 3);
        #pragma unroll
        for (int mf = 0; mf < 2; mf++)
            #pragma unroll
            for (int hf = 0; hf < 2; hf++) {
                int r = rb + 16 * mf + 8 * hf;
                float bv = __ldg(&bqkv[257 + r]);
                float c0 = cv_s[r], c1 = cv_s[256 + r];
                #pragma unroll
                for (int nf = 0; nf < 16; nf++) {
                    float cv = (nf < 8) ? c0 : c1;
                    float g0 = fmaxf(acc[mf][nf][2 * hf + 0] + bv, 0.f) * cv;
                    float g1 = fmaxf(acc[mf][nf][2 * hf + 1] + bv, 0.f) * cv;
                    uint32_t off = ((uint32_t)r * XROW + 8 * nf + cb) * 2;
                    *(uint32_t*)(smc + OFF_XH + off) = pack2h(g0, g1);
                }
            }
    }
    __syncthreads();            // G tile visible

    #pragma unroll
    for (int i = 0; i < 2; i++)
        #pragma unroll
        for (int j = 0; j < 16; j++)
            #pragma unroll
            for (int k = 0; k < 4; k++) acc[i][j][k] = 0.f;

    // ================= GEMM2: OUT = Wout . G =================
    gemm_main(&sc_WF[1][0][0][0][0], smb, acc, tid);

    {   // epi2: + bout -> global out (128 contiguous cols per row)
        float* ob = out + (size_t)b * 1048576 + (size_t)hp * 128;
        const int rb = wid * 32 + (lane >> 2);
        const int cb = 2 * (lane & 3);
        #pragma unroll
        for (int mf = 0; mf < 2; mf++)
            #pragma unroll
            for (int hf = 0; hf < 2; hf++) {
                int r = rb + 16 * mf + 8 * hf;
                float bo = __ldg(&bout[r]);
                #pragma unroll
                for (int nf = 0; nf < 16; nf++) {
                    float2 v;
                    v.x = acc[mf][nf][2 * hf + 0] + bo;
                    v.y = acc[mf][nf][2 * hf + 1] + bo;
                    *(float2*)(ob + (size_t)r * 4096 + 8 * nf + cb) = v;
                }
            }
    }
}

// ============================================================================
extern "C" void kernel_launch(void* const* d_in, const int* in_sizes, int n_in,
                              void* d_out, int out_size)
{
    const float* x    = (const float*)d_in[0];
    const float* Wqkv = (const float*)d_in[1];
    const float* bqkv = (const float*)d_in[2];
    const float* Wout = (const float*)d_in[3];
    const float* bout = (const float*)d_in[4];
    float* out = (float*)d_out;

    cudaFuncSetAttribute(sepattn_tc,
                         cudaFuncAttributeMaxDynamicSharedMemorySize, SMEM_BYTES);
    prep_kernel<<<64, 256>>>(Wqkv, Wout);
    sepattn_tc<<<1024, 256, SMEM_BYTES>>>(x, Wqkv, bqkv, bout, out);
}

// round 13
// speedup vs baseline: 1.3094x; 1.3094x over previous
#include <cuda_runtime.h>
#include <cuda_fp16.h>
#include <cstdint>

// ============================================================================
// SeparableAttention — round 12: round-10 structure (N=64/block, 2 CTAs/SM)
// with single-term fp16 W (hi only). 1 MMA per fragment pair.
//   - W pre-split to per-fragment fp16 uint4 tables -> A = single LDG.128.
//   - B (Xh fp16 tile) resident in smem via ldmatrix.trans.
//   - phase 1 (softmax/xs/cv) exact fp32 via Xh+Xl reconstruction.
// ============================================================================

#define OFF_XH   0                         // Xh fp16 [256][72] = 36864 B
#define OFF_SCR  36864                     // Xl fp16 tile / Wks fp32 alias
#define OFF_TAIL 73728
#define SMEM_BYTES (OFF_TAIL + 8192)       // 81920 B -> 2 CTAs/SM

// W fragments (hi only): [gemm][ks][mtile][lane]
__device__ uint4 sc_WF[2][16][16][32];     // 256 KB

// ---------------------------- helpers ---------------------------------------
__device__ __forceinline__ uint32_t smem_u32(const void* p) {
    uint32_t a;
    asm("{ .reg .u64 t; cvta.to.shared.u64 t, %1; cvt.u32.u64 %0, t; }"
        : "=r"(a) : "l"(p));
    return a;
}
__device__ __forceinline__ uint32_t pack2h(float a, float b) {
    __half2 t = __floats2half2_rn(a, b);
    return *reinterpret_cast<uint32_t*>(&t);
}
__device__ __forceinline__ float h_hi(float v) {
    return __half2float(__float2half_rn(v));
}

#define LDM4T(r0, r1, r2, r3, a) \
    asm volatile("ldmatrix.sync.aligned.m8n8.x4.trans.shared.b16 {%0,%1,%2,%3}, [%4];" \
        : "=r"(r0), "=r"(r1), "=r"(r2), "=r"(r3) : "r"(a))
#define MMA4(d, a, b) \
    asm volatile("mma.sync.aligned.m16n8k16.row.col.f32.f16.f16.f32 " \
        "{%0,%1,%2,%3}, {%4,%5,%6,%7}, {%8,%9}, {%0,%1,%2,%3};" \
        : "+f"((d)[0]), "+f"((d)[1]), "+f"((d)[2]), "+f"((d)[3]) \
        : "r"((a).x), "r"((a).y), "r"((a).z), "r"((a).w), \
          "r"((b)[0]), "r"((b)[1]))

// ============================================================================
// prep: per-fragment fp16 (hi) W tables, mma.m16n8k16 A layout.
//   lane l -> g=l>>2, t=l&3; rows {g, g+8}, cols {2t,2t+1, 2t+8,2t+9}.
// ============================================================================
__global__ void prep_kernel(const float* __restrict__ Wqkv,
                            const float* __restrict__ Wout)
{
    int idx = blockIdx.x * 256 + threadIdx.x;   // 16384 threads
    int lane  = idx & 31;
    int mtile = (idx >> 5) & 15;
    int ks    = (idx >> 9) & 15;
    int gemm  = idx >> 13;
    const float* W = gemm ? Wout : (Wqkv + (size_t)257 * 256);

    int g = lane >> 2, t = lane & 3;
    int r0 = mtile * 16 + g, r1 = r0 + 8;
    int c0 = ks * 16 + 2 * t, c2 = c0 + 8;

    uint4 hi;
    hi.x = pack2h(W[r0 * 256 + c0], W[r0 * 256 + c0 + 1]);
    hi.y = pack2h(W[r1 * 256 + c0], W[r1 * 256 + c0 + 1]);
    hi.z = pack2h(W[r0 * 256 + c2], W[r0 * 256 + c2 + 1]);
    hi.w = pack2h(W[r1 * 256 + c2], W[r1 * 256 + c2 + 1]);
    sc_WF[gemm][ks][mtile][lane] = hi;
}

// ============================================================================
// One 256x64x256 GEMM: A fragments via LDG.128 (double-buffered in regs),
// B = Xh smem tile via ldmatrix.trans. No barriers inside.
// ============================================================================
__device__ __forceinline__ void gemm_main(const uint4* __restrict__ WF,
                                          uint32_t smb,
                                          float acc[2][8][4], int tid)
{
    const int lane = tid & 31, wid = tid >> 5;
    const int lrow = (lane & 7) + ((lane >> 3) & 1) * 8;
    const int lcol = (lane >> 4) * 8;

    uint4 bh[2][2];
    #pragma unroll
    for (int mf = 0; mf < 2; mf++)
        bh[0][mf] = __ldg(WF + (wid * 2 + mf) * 32 + lane);

    #pragma unroll
    for (int ks = 0; ks < 16; ks++) {
        const int p = ks & 1;
        if (ks < 15) {
            #pragma unroll
            for (int mf = 0; mf < 2; mf++)
                bh[1 - p][mf] =
                    __ldg(WF + ((ks + 1) * 16 + wid * 2 + mf) * 32 + lane);
        }
        uint32_t Bh[8][2];
        const int k0 = ks * 16;
        #pragma unroll
        for (int nn = 0; nn < 4; nn++) {
            uint32_t boff = (uint32_t)(k0 + lrow) * 144 + (nn * 16 + lcol) * 2;
            uint32_t t0, t1, t2, t3;
            LDM4T(t0, t1, t2, t3, smb + OFF_XH + boff);
            Bh[2 * nn][0] = t0;     Bh[2 * nn][1] = t1;
            Bh[2 * nn + 1][0] = t2; Bh[2 * nn + 1][1] = t3;
        }
        #pragma unroll
        for (int nf = 0; nf < 8; nf++) {
            MMA4(acc[0][nf], bh[p][0], Bh[nf]);
            MMA4(acc[1][nf], bh[p][1], Bh[nf]);
        }
    }
}

// ============================================================================
__global__ __launch_bounds__(256, 2)
void sepattn_tc(const float* __restrict__ x,
                const float* __restrict__ Wqkv,
                const float* __restrict__ bqkv,
                const float* __restrict__ bout,
                float* __restrict__ out)
{
    extern __shared__ char smc[];
    float* tail = (float*)(smc + OFF_TAIL);
    float* cv_s = tail;                        // 256
    float* q_s  = tail + 256;                  // 64
    float* s_s  = tail + 320;                  // 64
    float* xs_s = tail + 384;                  // 256
    float* Wq_s = tail + 640;                  // 256
    float* qp   = tail + 896;                  // 256
    float* red  = tail + 1152;                 // 8
    float* Wks  = (float*)(smc + OFF_SCR);     // phase-1b alias over Xl
    const uint32_t smb = smem_u32(smc);

    const int tid = threadIdx.x;
    const int lane = tid & 31, wid = tid >> 5;
    const int b = blockIdx.x >> 6;
    const int h = blockIdx.x & 63;

    // -------- phase 0: load X tile, split Xh (fp16) + Xl (fp16) -------------
    const float2* x2 = (const float2*)(x + (size_t)b * 256 * 4096);
    #pragma unroll
    for (int k = 0; k < 32; k++) {
        int idx = tid + k * 256;
        int w2 = idx & 31, c = idx >> 5;
        float2 v = __ldg(&x2[c * 2048 + h * 32 + w2]);
        float h0 = h_hi(v.x), h1 = h_hi(v.y);
        uint32_t off = ((uint32_t)c * 72 + 2 * w2) * 2;
        *(uint32_t*)(smc + OFF_XH + off) = pack2h(h0, h1);
        *(uint32_t*)(smc + OFF_SCR + off) = pack2h(v.x - h0, v.y - h1);
    }
    if (tid < 64) {
        float4 v = __ldg(&((const float4*)Wqkv)[tid]);
        *(float4*)&Wq_s[4 * tid] = v;
    }
    __syncthreads();

    // -------- phase 1: q (256 thr), softmax, xs, cv -------------------------
    {
        int w = tid & 63, part = tid >> 6;
        const __half* XH = (const __half*)(smc + OFF_XH);
        const __half* XL = (const __half*)(smc + OFF_SCR);
        float a = 0.f;
        #pragma unroll 8
        for (int c = part * 64; c < part * 64 + 64; c++)
            a = fmaf(Wq_s[c],
                     __half2float(XH[c * 72 + w]) + __half2float(XL[c * 72 + w]),
                     a);
        qp[part * 64 + w] = a;
    }
    __syncthreads();
    if (tid < 64)
        q_s[tid] = qp[tid] + qp[64 + tid] + qp[128 + tid] + qp[192 + tid]
                   + __ldg(&bqkv[0]);
    __syncthreads();
    if (tid < 32) {
        float m = fmaxf(q_s[tid], q_s[tid + 32]);
        #pragma unroll
        for (int o = 16; o > 0; o >>= 1)
            m = fmaxf(m, __shfl_xor_sync(0xffffffffu, m, o));
        if (tid == 0) red[0] = m;
    }
    __syncthreads();
    if (tid < 64) q_s[tid] = __expf(q_s[tid] - red[0]);
    __syncthreads();
    if (tid < 32) {
        float s = q_s[tid] + q_s[tid + 32];
        #pragma unroll
        for (int o = 16; o > 0; o >>= 1) s += __shfl_xor_sync(0xffffffffu, s, o);
        if (tid == 0) red[1] = 1.0f / s;
    }
    __syncthreads();
    if (tid < 64) s_s[tid] = q_s[tid] * red[1];
    __syncthreads();

    {   // xs[c] = sum_w (Xh+Xl)[c,w] s[w]
        const __half2* XH2 = (const __half2*)(smc + OFF_XH);
        const __half2* XL2 = (const __half2*)(smc + OFF_SCR);
        float a = 0.f;
        #pragma unroll 8
        for (int j = 0; j < 32; j++) {
            int jj = (j + tid) & 31;
            float2 hf = __half22float2(XH2[tid * 36 + jj]);
            float2 lf = __half22float2(XL2[tid * 36 + jj]);
            a = fmaf(hf.x + lf.x, s_s[2 * jj], a);
            a = fmaf(hf.y + lf.y, s_s[2 * jj + 1], a);
        }
        xs_s[tid] = a;
    }

    // cv[c] = Wk[c,:].xs + bk[c]  (Xl dead -> Wks scratch)
    float acc_cv = __ldg(&bqkv[1 + tid]);
    const float4* W4full = (const float4*)Wqkv;
    for (int ec = 0; ec < 8; ec++) {
        __syncthreads();
        #pragma unroll
        for (int i = 0; i < 8; i++) {
            int idx = tid + i * 256;
            int r = idx >> 3, q = idx & 7;
            float4 v = __ldg(&W4full[(size_t)(1 + r) * 64 + ec * 8 + q]);
            *(float4*)&Wks[r * 36 + q * 4] = v;
        }
        __syncthreads();
        #pragma unroll 8
        for (int e = 0; e < 32; e++) {
            int er = (e + tid) & 31;
            acc_cv = fmaf(Wks[tid * 36 + er], xs_s[ec * 32 + er], acc_cv);
        }
    }
    cv_s[tid] = acc_cv;
    // cv_s visibility for epi1 covered by post-GEMM1 __syncthreads.

    float acc[2][8][4];
    #pragma unroll
    for (int i = 0; i < 2; i++)
        #pragma unroll
        for (int j = 0; j < 8; j++)
            #pragma unroll
            for (int k = 0; k < 4; k++) acc[i][j][k] = 0.f;

    // ================= GEMM1: V = Wv . X =================
    gemm_main(&sc_WF[0][0][0][0], smb, acc, tid);

    __syncthreads();            // all B reads done before overwriting Xh
    {   // epi1: g = relu(v+bv)*cv -> Xh
        const int rb = wid * 32 + (lane >> 2);
        const int cb = 2 * (lane & 3);
        #pragma unroll
        for (int mf = 0; mf < 2; mf++)
            #pragma unroll
            for (int hf = 0; hf < 2; hf++) {
                int r = rb + 16 * mf + 8 * hf;
                float bv = __ldg(&bqkv[257 + r]);
                float cv = cv_s[r];
                #pragma unroll
                for (int nf = 0; nf < 8; nf++) {
                    float g0 = fmaxf(acc[mf][nf][2 * hf + 0] + bv, 0.f) * cv;
                    float g1 = fmaxf(acc[mf][nf][2 * hf + 1] + bv, 0.f) * cv;
                    uint32_t off = ((uint32_t)r * 72 + 8 * nf + cb) * 2;
                    *(uint32_t*)(smc + OFF_XH + off) = pack2h(g0, g1);
                }
            }
    }
    __syncthreads();            // G tile visible to all warps

    #pragma unroll
    for (int i = 0; i < 2; i++)
        #pragma unroll
        for (int j = 0; j < 8; j++)
            #pragma unroll
            for (int k = 0; k < 4; k++) acc[i][j][k] = 0.f;

    // ================= GEMM2: OUT = Wout . G =================
    gemm_main(&sc_WF[1][0][0][0], smb, acc, tid);

    {   // epi2: + bout -> global out
        float* ob = out + (size_t)b * 1048576 + (size_t)h * 64;
        const int rb = wid * 32 + (lane >> 2);
        const int cb = 2 * (lane & 3);
        #pragma unroll
        for (int mf = 0; mf < 2; mf++)
            #pragma unroll
            for (int hf = 0; hf < 2; hf++) {
                int r = rb + 16 * mf + 8 * hf;
                float bo = __ldg(&bout[r]);
                #pragma unroll
                for (int nf = 0; nf < 8; nf++) {
                    float2 v;
                    v.x = acc[mf][nf][2 * hf + 0] + bo;
                    v.y = acc[mf][nf][2 * hf + 1] + bo;
                    *(float2*)(ob + (size_t)r * 4096 + 8 * nf + cb) = v;
                }
            }
    }
}

// ============================================================================
extern "C" void kernel_launch(void* const* d_in, const int* in_sizes, int n_in,
                              void* d_out, int out_size)
{
    const float* x    = (const float*)d_in[0];
    const float* Wqkv = (const float*)d_in[1];
    const float* bqkv = (const float*)d_in[2];
    const float* Wout = (const float*)d_in[3];
    const float* bout = (const float*)d_in[4];
    float* out = (float*)d_out;

    cudaFuncSetAttribute(sepattn_tc,
                         cudaFuncAttributeMaxDynamicSharedMemorySize, SMEM_BYTES);
    prep_kernel<<<64, 256>>>(Wqkv, Wout);
    sepattn_tc<<<2048, 256, SMEM_BYTES>>>(x, Wqkv, bqkv, bout, out);
}

// round 14
// speedup vs baseline: 1.7996x; 1.3744x over previous
#include <cuda_runtime.h>
#include <cuda_fp16.h>
#include <cstdint>

// ============================================================================
// SeparableAttention — round 14: round-13 structure + cv via tensor-core MMA.
//   - W (Wv, Wout) single-term fp16 per-fragment LDG tables (round 13).
//   - NEW: Wk hi/lo fragment tables; cv = Wk . xs computed by MMA against a
//     tiny 256x8 B-tile holding {xs_hi, xs_lo}; scalar Wk streaming deleted.
//   - B (Xh fp16 tile) resident in smem via ldmatrix.trans; phase-1 softmax
//     exact fp32 via Xh+Xl reconstruction.
// ============================================================================

#define OFF_XH   0                         // Xh fp16 [256][72] = 36864 B
#define OFF_SCR  36864                     // Xl fp16 tile (phase 0/1 only)
#define OFF_TAIL 73728
#define OFF_BX   (OFF_TAIL + 4608)         // 256 x 16B rows (xs_hi, xs_lo, 0..)
#define SMEM_BYTES (OFF_BX + 4096)         // 82432 B -> 2 CTAs/SM

// W fragments: [set][ks][mtile][lane]; set 0=Wv_hi 1=Wout_hi 2=Wk_hi 3=Wk_lo
__device__ uint4 sc_WF[4][16][16][32];     // 512 KB

// ---------------------------- helpers ---------------------------------------
__device__ __forceinline__ uint32_t smem_u32(const void* p) {
    uint32_t a;
    asm("{ .reg .u64 t; cvta.to.shared.u64 t, %1; cvt.u32.u64 %0, t; }"
        : "=r"(a) : "l"(p));
    return a;
}
__device__ __forceinline__ uint32_t pack2h(float a, float b) {
    __half2 t = __floats2half2_rn(a, b);
    return *reinterpret_cast<uint32_t*>(&t);
}
__device__ __forceinline__ float h_hi(float v) {
    return __half2float(__float2half_rn(v));
}

#define LDM4T(r0, r1, r2, r3, a) \
    asm volatile("ldmatrix.sync.aligned.m8n8.x4.trans.shared.b16 {%0,%1,%2,%3}, [%4];" \
        : "=r"(r0), "=r"(r1), "=r"(r2), "=r"(r3) : "r"(a))
#define MMA4(d, a, b) \
    asm volatile("mma.sync.aligned.m16n8k16.row.col.f32.f16.f16.f32 " \
        "{%0,%1,%2,%3}, {%4,%5,%6,%7}, {%8,%9}, {%0,%1,%2,%3};" \
        : "+f"((d)[0]), "+f"((d)[1]), "+f"((d)[2]), "+f"((d)[3]) \
        : "r"((a).x), "r"((a).y), "r"((a).z), "r"((a).w), \
          "r"((b)[0]), "r"((b)[1]))

// ============================================================================
// prep: per-fragment fp16 W tables, mma.m16n8k16 A layout.
//   lane l -> g=l>>2, t=l&3; rows {g, g+8}, cols {2t,2t+1, 2t+8,2t+9}.
//   set 0: Wv hi   set 1: Wout hi   set 2: Wk hi   set 3: Wk lo
// ============================================================================
__global__ void prep_kernel(const float* __restrict__ Wqkv,
                            const float* __restrict__ Wout)
{
    int idx = blockIdx.x * 256 + threadIdx.x;   // 32768 threads
    int lane  = idx & 31;
    int mtile = (idx >> 5) & 15;
    int ks    = (idx >> 9) & 15;
    int set   = idx >> 13;                      // 0..3

    const float* W = (set == 0) ? (Wqkv + (size_t)257 * 256)
                   : (set == 1) ? Wout
                                : (Wqkv + 256);  // Wk rows 1..256
    const bool lo = (set == 3);

    int g = lane >> 2, t = lane & 3;
    int r0 = mtile * 16 + g, r1 = r0 + 8;
    int c0 = ks * 16 + 2 * t, c2 = c0 + 8;

    float w00 = W[r0 * 256 + c0], w01 = W[r0 * 256 + c0 + 1];
    float w10 = W[r1 * 256 + c0], w11 = W[r1 * 256 + c0 + 1];
    float w02 = W[r0 * 256 + c2], w03 = W[r0 * 256 + c2 + 1];
    float w12 = W[r1 * 256 + c2], w13 = W[r1 * 256 + c2 + 1];

    if (lo) {
        w00 -= h_hi(w00); w01 -= h_hi(w01); w10 -= h_hi(w10); w11 -= h_hi(w11);
        w02 -= h_hi(w02); w03 -= h_hi(w03); w12 -= h_hi(w12); w13 -= h_hi(w13);
    }
    uint4 v;
    v.x = pack2h(w00, w01);
    v.y = pack2h(w10, w11);
    v.z = pack2h(w02, w03);
    v.w = pack2h(w12, w13);
    sc_WF[set][ks][mtile][lane] = v;
}

// ============================================================================
// One 256x64x256 GEMM: A fragments via LDG.128 (double-buffered in regs),
// B = Xh smem tile via ldmatrix.trans. No barriers inside.
// ============================================================================
__device__ __forceinline__ void gemm_main(const uint4* __restrict__ WF,
                                          uint32_t smb,
                                          float acc[2][8][4], int tid)
{
    const int lane = tid & 31, wid = tid >> 5;
    const int lrow = (lane & 7) + ((lane >> 3) & 1) * 8;
    const int lcol = (lane >> 4) * 8;

    uint4 bh[2][2];
    #pragma unroll
    for (int mf = 0; mf < 2; mf++)
        bh[0][mf] = __ldg(WF + (wid * 2 + mf) * 32 + lane);

    #pragma unroll
    for (int ks = 0; ks < 16; ks++) {
        const int p = ks & 1;
        if (ks < 15) {
            #pragma unroll
            for (int mf = 0; mf < 2; mf++)
                bh[1 - p][mf] =
                    __ldg(WF + ((ks + 1) * 16 + wid * 2 + mf) * 32 + lane);
        }
        uint32_t Bh[8][2];
        const int k0 = ks * 16;
        #pragma unroll
        for (int nn = 0; nn < 4; nn++) {
            uint32_t boff = (uint32_t)(k0 + lrow) * 144 + (nn * 16 + lcol) * 2;
            uint32_t t0, t1, t2, t3;
            LDM4T(t0, t1, t2, t3, smb + OFF_XH + boff);
            Bh[2 * nn][0] = t0;     Bh[2 * nn][1] = t1;
            Bh[2 * nn + 1][0] = t2; Bh[2 * nn + 1][1] = t3;
        }
        #pragma unroll
        for (int nf = 0; nf < 8; nf++) {
            MMA4(acc[0][nf], bh[p][0], Bh[nf]);
            MMA4(acc[1][nf], bh[p][1], Bh[nf]);
        }
    }
}

// ============================================================================
__global__ __launch_bounds__(256, 2)
void sepattn_tc(const float* __restrict__ x,
                const float* __restrict__ Wqkv,
                const float* __restrict__ bqkv,
                const float* __restrict__ bout,
                float* __restrict__ out)
{
    extern __shared__ char smc[];
    float* tail = (float*)(smc + OFF_TAIL);
    float* cv_s = tail;                        // 256
    float* q_s  = tail + 256;                  // 64
    float* s_s  = tail + 320;                  // 64
    float* Wq_s = tail + 384;                  // 256
    float* qp   = tail + 640;                  // 256
    float* red  = tail + 896;                  // 8
    const uint32_t smb = smem_u32(smc);

    const int tid = threadIdx.x;
    const int lane = tid & 31, wid = tid >> 5;
    const int b = blockIdx.x >> 6;
    const int h = blockIdx.x & 63;

    // -------- phase 0: load X tile, split Xh (fp16) + Xl (fp16) -------------
    const float2* x2 = (const float2*)(x + (size_t)b * 256 * 4096);
    #pragma unroll
    for (int k = 0; k < 32; k++) {
        int idx = tid + k * 256;
        int w2 = idx & 31, c = idx >> 5;
        float2 v = __ldg(&x2[c * 2048 + h * 32 + w2]);
        float h0 = h_hi(v.x), h1 = h_hi(v.y);
        uint32_t off = ((uint32_t)c * 72 + 2 * w2) * 2;
        *(uint32_t*)(smc + OFF_XH + off) = pack2h(h0, h1);
        *(uint32_t*)(smc + OFF_SCR + off) = pack2h(v.x - h0, v.y - h1);
    }
    if (tid < 64) {
        float4 v = __ldg(&((const float4*)Wqkv)[tid]);
        *(float4*)&Wq_s[4 * tid] = v;
    }
    __syncthreads();

    // -------- phase 1: q (256 thr), softmax ---------------------------------
    {
        int w = tid & 63, part = tid >> 6;
        const __half* XH = (const __half*)(smc + OFF_XH);
        const __half* XL = (const __half*)(smc + OFF_SCR);
        float a = 0.f;
        #pragma unroll 8
        for (int c = part * 64; c < part * 64 + 64; c++)
            a = fmaf(Wq_s[c],
                     __half2float(XH[c * 72 + w]) + __half2float(XL[c * 72 + w]),
                     a);
        qp[part * 64 + w] = a;
    }
    __syncthreads();
    if (tid < 64)
        q_s[tid] = qp[tid] + qp[64 + tid] + qp[128 + tid] + qp[192 + tid]
                   + __ldg(&bqkv[0]);
    __syncthreads();
    if (tid < 32) {
        float m = fmaxf(q_s[tid], q_s[tid + 32]);
        #pragma unroll
        for (int o = 16; o > 0; o >>= 1)
            m = fmaxf(m, __shfl_xor_sync(0xffffffffu, m, o));
        if (tid == 0) red[0] = m;
    }
    __syncthreads();
    if (tid < 64) q_s[tid] = __expf(q_s[tid] - red[0]);
    __syncthreads();
    if (tid < 32) {
        float s = q_s[tid] + q_s[tid + 32];
        #pragma unroll
        for (int o = 16; o > 0; o >>= 1) s += __shfl_xor_sync(0xffffffffu, s, o);
        if (tid == 0) red[1] = 1.0f / s;
    }
    __syncthreads();
    if (tid < 64) s_s[tid] = q_s[tid] * red[1];
    __syncthreads();

    // -------- xs[c] = sum_w (Xh+Xl)[c,w] s[w], pack into BX tile ------------
    {
        const __half2* XH2 = (const __half2*)(smc + OFF_XH);
        const __half2* XL2 = (const __half2*)(smc + OFF_SCR);
        float a = 0.f;
        #pragma unroll 8
        for (int j = 0; j < 32; j++) {
            int jj = (j + tid) & 31;
            float2 hf = __half22float2(XH2[tid * 36 + jj]);
            float2 lf = __half22float2(XL2[tid * 36 + jj]);
            a = fmaf(hf.x + lf.x, s_s[2 * jj], a);
            a = fmaf(hf.y + lf.y, s_s[2 * jj + 1], a);
        }
        float ah = h_hi(a);
        uint4 row;
        row.x = pack2h(ah, a - ah);            // cols 0,1 = xs_hi, xs_lo
        row.y = 0u; row.z = 0u; row.w = 0u;    // cols 2..7 = 0
        *(uint4*)(smc + OFF_BX + (uint32_t)tid * 16) = row;
    }
    __syncthreads();

    // -------- cv = (Wk_hi + Wk_lo) . (xs_hi + xs_lo) via MMA ----------------
    {
        uint32_t bfr[16][2];
        #pragma unroll
        for (int c32 = 0; c32 < 8; c32++) {
            uint32_t t0, t1, t2, t3;
            LDM4T(t0, t1, t2, t3,
                  smb + OFF_BX + (uint32_t)(c32 * 32 + lane) * 16);
            bfr[2 * c32][0] = t0;     bfr[2 * c32][1] = t1;
            bfr[2 * c32 + 1][0] = t2; bfr[2 * c32 + 1][1] = t3;
        }
        float cva[2][4];
        #pragma unroll
        for (int mf = 0; mf < 2; mf++)
            #pragma unroll
            for (int k = 0; k < 4; k++) cva[mf][k] = 0.f;
        #pragma unroll
        for (int ks = 0; ks < 16; ks++) {
            #pragma unroll
            for (int mf = 0; mf < 2; mf++) {
                uint4 ah = __ldg(&sc_WF[2][ks][wid * 2 + mf][lane]);
                uint4 al = __ldg(&sc_WF[3][ks][wid * 2 + mf][lane]);
                MMA4(cva[mf], ah, bfr[ks]);
                MMA4(cva[mf], al, bfr[ks]);
            }
        }
        if ((lane & 3) == 0) {                 // cols 0,1 live on t==0 lanes
            int g = lane >> 2;
            #pragma unroll
            for (int mf = 0; mf < 2; mf++) {
                int r = wid * 32 + mf * 16 + g;
                cv_s[r]     = cva[mf][0] + cva[mf][1] + __ldg(&bqkv[1 + r]);
                cv_s[r + 8] = cva[mf][2] + cva[mf][3] + __ldg(&bqkv[9 + r]);
            }
        }
    }
    // cv_s visibility for epi1 covered by post-GEMM1 __syncthreads.

    float acc[2][8][4];
    #pragma unroll
    for (int i = 0; i < 2; i++)
        #pragma unroll
        for (int j = 0; j < 8; j++)
            #pragma unroll
            for (int k = 0; k < 4; k++) acc[i][j][k] = 0.f;

    // ================= GEMM1: V = Wv . X =================
    gemm_main(&sc_WF[0][0][0][0], smb, acc, tid);

    __syncthreads();            // all B reads done before overwriting Xh
    {   // epi1: g = relu(v+bv)*cv -> Xh
        const int rb = wid * 32 + (lane >> 2);
        const int cb = 2 * (lane & 3);
        #pragma unroll
        for (int mf = 0; mf < 2; mf++)
            #pragma unroll
            for (int hf = 0; hf < 2; hf++) {
                int r = rb + 16 * mf + 8 * hf;
                float bv = __ldg(&bqkv[257 + r]);
                float cv = cv_s[r];
                #pragma unroll
                for (int nf = 0; nf < 8; nf++) {
                    float g0 = fmaxf(acc[mf][nf][2 * hf + 0] + bv, 0.f) * cv;
                    float g1 = fmaxf(acc[mf][nf][2 * hf + 1] + bv, 0.f) * cv;
                    uint32_t off = ((uint32_t)r * 72 + 8 * nf + cb) * 2;
                    *(uint32_t*)(smc + OFF_XH + off) = pack2h(g0, g1);
                }
            }
    }
    __syncthreads();            // G tile visible to all warps

    #pragma unroll
    for (int i = 0; i < 2; i++)
        #pragma unroll
        for (int j = 0; j < 8; j++)
            #pragma unroll
            for (int k = 0; k < 4; k++) acc[i][j][k] = 0.f;

    // ================= GEMM2: OUT = Wout . G =================
    gemm_main(&sc_WF[1][0][0][0], smb, acc, tid);

    {   // epi2: + bout -> global out
        float* ob = out + (size_t)b * 1048576 + (size_t)h * 64;
        const int rb = wid * 32 + (lane >> 2);
        const int cb = 2 * (lane & 3);
        #pragma unroll
        for (int mf = 0; mf < 2; mf++)
            #pragma unroll
            for (int hf = 0; hf < 2; hf++) {
                int r = rb + 16 * mf + 8 * hf;
                float bo = __ldg(&bout[r]);
                #pragma unroll
                for (int nf = 0; nf < 8; nf++) {
                    float2 v;
                    v.x = acc[mf][nf][2 * hf + 0] + bo;
                    v.y = acc[mf][nf][2 * hf + 1] + bo;
                    *(float2*)(ob + (size_t)r * 4096 + 8 * nf + cb) = v;
                }
            }
    }
}

// ============================================================================
extern "C" void kernel_launch(void* const* d_in, const int* in_sizes, int n_in,
                              void* d_out, int out_size)
{
    const float* x    = (const float*)d_in[0];
    const float* Wqkv = (const float*)d_in[1];
    const float* bqkv = (const float*)d_in[2];
    const float* Wout = (const float*)d_in[3];
    const float* bout = (const float*)d_in[4];
    float* out = (float*)d_out;

    cudaFuncSetAttribute(sepattn_tc,
                         cudaFuncAttributeMaxDynamicSharedMemorySize, SMEM_BYTES);
    prep_kernel<<<128, 256>>>(Wqkv, Wout);
    sepattn_tc<<<2048, 256, SMEM_BYTES>>>(x, Wqkv, bqkv, bout, out);
}

// round 15
// speedup vs baseline: 1.8004x; 1.0004x over previous
#include <cuda_runtime.h>
#include <cuda_fp16.h>
#include <cstdint>

// ============================================================================
// SeparableAttention — round 15: ALL contractions on tensor cores.
//   q  = Wq.X   : MMA, Wq hi/lo A-table rows 0/1, B = Xh & Xl tiles (warps 0-3)
//   xs = X.s    : MMA, A = X via non-trans ldmatrix, B = {s_hi, s_lo} in regs
//   cv = Wk.xs  : MMA against BX tile (round 14)
//   V/OUT GEMMs : single-term fp16 W fragment tables (round 13)
//   Softmax exact fp32; bias bq dropped (softmax-invariant).
// ============================================================================

#define OFF_XH   0                         // Xh fp16 [256][72] = 36864 B
#define OFF_SCR  36864                     // Xl fp16 tile (kept whole kernel)
#define OFF_TAIL 73728
#define OFF_BX   (OFF_TAIL + 4608)         // 256 x 16B rows (xs_hi, xs_lo, 0..)
#define SMEM_BYTES (OFF_BX + 4096)         // 82432 B -> 2 CTAs/SM

// W fragments: [set][ks][mtile][lane]; 0=Wv_hi 1=Wout_hi 2=Wk_hi 3=Wk_lo
__device__ uint4 sc_WF[4][16][16][32];     // 512 KB
__device__ uint4 sc_WQ[16][32];            // Wq hi/lo rows 0/1, 8 KB

// ---------------------------- helpers ---------------------------------------
__device__ __forceinline__ uint32_t smem_u32(const void* p) {
    uint32_t a;
    asm("{ .reg .u64 t; cvta.to.shared.u64 t, %1; cvt.u32.u64 %0, t; }"
        : "=r"(a) : "l"(p));
    return a;
}
__device__ __forceinline__ uint32_t pack2h(float a, float b) {
    __half2 t = __floats2half2_rn(a, b);
    return *reinterpret_cast<uint32_t*>(&t);
}
__device__ __forceinline__ uint32_t pack_hh(__half a, __half b) {
    return (uint32_t)__half_as_ushort(a) | ((uint32_t)__half_as_ushort(b) << 16);
}
__device__ __forceinline__ float h_hi(float v) {
    return __half2float(__float2half_rn(v));
}

#define LDM4(r0, r1, r2, r3, a) \
    asm volatile("ldmatrix.sync.aligned.m8n8.x4.shared.b16 {%0,%1,%2,%3}, [%4];" \
        : "=r"(r0), "=r"(r1), "=r"(r2), "=r"(r3) : "r"(a))
#define LDM4T(r0, r1, r2, r3, a) \
    asm volatile("ldmatrix.sync.aligned.m8n8.x4.trans.shared.b16 {%0,%1,%2,%3}, [%4];" \
        : "=r"(r0), "=r"(r1), "=r"(r2), "=r"(r3) : "r"(a))
#define MMA4(d, a, b) \
    asm volatile("mma.sync.aligned.m16n8k16.row.col.f32.f16.f16.f32 " \
        "{%0,%1,%2,%3}, {%4,%5,%6,%7}, {%8,%9}, {%0,%1,%2,%3};" \
        : "+f"((d)[0]), "+f"((d)[1]), "+f"((d)[2]), "+f"((d)[3]) \
        : "r"((a).x), "r"((a).y), "r"((a).z), "r"((a).w), \
          "r"((b)[0]), "r"((b)[1]))

// ============================================================================
// prep: per-fragment fp16 W tables (mma.m16n8k16 A layout) + Wq table.
// ============================================================================
__global__ void prep_kernel(const float* __restrict__ Wqkv,
                            const float* __restrict__ Wout)
{
    int idx = blockIdx.x * 256 + threadIdx.x;   // 130*256 = 33280 threads
    int lane = idx & 31;

    if (idx < 32768) {
        int mtile = (idx >> 5) & 15;
        int ks    = (idx >> 9) & 15;
        int set   = idx >> 13;                  // 0..3
        const float* W = (set == 0) ? (Wqkv + (size_t)257 * 256)
                       : (set == 1) ? Wout
                                    : (Wqkv + 256);  // Wk rows 1..256
        const bool lo = (set == 3);

        int g = lane >> 2, t = lane & 3;
        int r0 = mtile * 16 + g, r1 = r0 + 8;
        int c0 = ks * 16 + 2 * t, c2 = c0 + 8;

        float w00 = W[r0 * 256 + c0], w01 = W[r0 * 256 + c0 + 1];
        float w10 = W[r1 * 256 + c0], w11 = W[r1 * 256 + c0 + 1];
        float w02 = W[r0 * 256 + c2], w03 = W[r0 * 256 + c2 + 1];
        float w12 = W[r1 * 256 + c2], w13 = W[r1 * 256 + c2 + 1];
        if (lo) {
            w00 -= h_hi(w00); w01 -= h_hi(w01); w10 -= h_hi(w10); w11 -= h_hi(w11);
            w02 -= h_hi(w02); w03 -= h_hi(w03); w12 -= h_hi(w12); w13 -= h_hi(w13);
        }
        uint4 v;
        v.x = pack2h(w00, w01); v.y = pack2h(w10, w11);
        v.z = pack2h(w02, w03); v.w = pack2h(w12, w13);
        sc_WF[set][ks][mtile][lane] = v;
    } else {
        int i2 = idx - 32768;                   // 0..511
        int ks = (i2 >> 5) & 15;
        int g = lane >> 2, t = lane & 3;
        int c0 = ks * 16 + 2 * t, c2 = c0 + 8;
        const float* Wq = Wqkv;                 // row 0
        uint4 v; v.x = 0u; v.y = 0u; v.z = 0u; v.w = 0u;
        if (g == 0) {                           // row 0 = Wq_hi
            v.x = pack2h(h_hi(Wq[c0]), h_hi(Wq[c0 + 1]));
            v.z = pack2h(h_hi(Wq[c2]), h_hi(Wq[c2 + 1]));
        } else if (g == 1) {                    // row 1 = Wq_lo
            v.x = pack2h(Wq[c0] - h_hi(Wq[c0]), Wq[c0 + 1] - h_hi(Wq[c0 + 1]));
            v.z = pack2h(Wq[c2] - h_hi(Wq[c2]), Wq[c2 + 1] - h_hi(Wq[c2 + 1]));
        }
        sc_WQ[ks][lane] = v;
    }
}

// ============================================================================
// One 256x64x256 GEMM: A fragments via LDG.128 (double-buffered in regs),
// B = Xh smem tile via ldmatrix.trans. No barriers inside.
// ============================================================================
__device__ __forceinline__ void gemm_main(const uint4* __restrict__ WF,
                                          uint32_t smb,
                                          float acc[2][8][4], int tid)
{
    const int lane = tid & 31, wid = tid >> 5;
    const int lrow = (lane & 7) + ((lane >> 3) & 1) * 8;
    const int lcol = (lane >> 4) * 8;

    uint4 bh[2][2];
    #pragma unroll
    for (int mf = 0; mf < 2; mf++)
        bh[0][mf] = __ldg(WF + (wid * 2 + mf) * 32 + lane);

    #pragma unroll
    for (int ks = 0; ks < 16; ks++) {
        const int p = ks & 1;
        if (ks < 15) {
            #pragma unroll
            for (int mf = 0; mf < 2; mf++)
                bh[1 - p][mf] =
                    __ldg(WF + ((ks + 1) * 16 + wid * 2 + mf) * 32 + lane);
        }
        uint32_t Bh[8][2];
        const int k0 = ks * 16;
        #pragma unroll
        for (int nn = 0; nn < 4; nn++) {
            uint32_t boff = (uint32_t)(k0 + lrow) * 144 + (nn * 16 + lcol) * 2;
            uint32_t t0, t1, t2, t3;
            LDM4T(t0, t1, t2, t3, smb + OFF_XH + boff);
            Bh[2 * nn][0] = t0;     Bh[2 * nn][1] = t1;
            Bh[2 * nn + 1][0] = t2; Bh[2 * nn + 1][1] = t3;
        }
        #pragma unroll
        for (int nf = 0; nf < 8; nf++) {
            MMA4(acc[0][nf], bh[p][0], Bh[nf]);
            MMA4(acc[1][nf], bh[p][1], Bh[nf]);
        }
    }
}

// ============================================================================
__global__ __launch_bounds__(256, 2)
void sepattn_tc(const float* __restrict__ x,
                const float* __restrict__ Wqkv,
                const float* __restrict__ bqkv,
                const float* __restrict__ bout,
                float* __restrict__ out)
{
    extern __shared__ char smc[];
    float* tail = (float*)(smc + OFF_TAIL);
    float* cv_s = tail;                        // 256
    float* q_s  = tail + 256;                  // 64
    float* red  = tail + 320;                  // 8
    __half2* sp = (__half2*)(tail + 328);      // 64 x {s_hi, s_lo}
    const uint32_t smb = smem_u32(smc);

    const int tid = threadIdx.x;
    const int lane = tid & 31, wid = tid >> 5;
    const int lrow = (lane & 7) + ((lane >> 3) & 1) * 8;
    const int lcol = (lane >> 4) * 8;
    const int b = blockIdx.x >> 6;
    const int h = blockIdx.x & 63;

    // -------- phase 0: load X tile, split Xh (fp16) + Xl (fp16) -------------
    const float2* x2 = (const float2*)(x + (size_t)b * 256 * 4096);
    #pragma unroll
    for (int k = 0; k < 32; k++) {
        int idx = tid + k * 256;
        int w2 = idx & 31, c = idx >> 5;
        float2 v = __ldg(&x2[c * 2048 + h * 32 + w2]);
        float h0 = h_hi(v.x), h1 = h_hi(v.y);
        uint32_t off = ((uint32_t)c * 72 + 2 * w2) * 2;
        *(uint32_t*)(smc + OFF_XH + off) = pack2h(h0, h1);
        *(uint32_t*)(smc + OFF_SCR + off) = pack2h(v.x - h0, v.y - h1);
    }
    __syncthreads();

    // -------- q = Wq.X via MMA (warps 0-3, n16 span each) -------------------
    if (wid < 4) {
        float dq[2][4];
        #pragma unroll
        for (int i = 0; i < 2; i++)
            #pragma unroll
            for (int k = 0; k < 4; k++) dq[i][k] = 0.f;
        #pragma unroll
        for (int ks = 0; ks < 16; ks++) {
            uint4 aq = __ldg(&sc_WQ[ks][lane]);
            uint32_t boff = (uint32_t)(ks * 16 + lrow) * 144
                            + (wid * 16 + lcol) * 2;
            uint32_t t0, t1, t2, t3;
            uint32_t B0[2], B1[2];
            LDM4T(t0, t1, t2, t3, smb + OFF_XH + boff);
            B0[0] = t0; B0[1] = t1; B1[0] = t2; B1[1] = t3;
            MMA4(dq[0], aq, B0);
            MMA4(dq[1], aq, B1);
            LDM4T(t0, t1, t2, t3, smb + OFF_SCR + boff);
            B0[0] = t0; B0[1] = t1; B1[0] = t2; B1[1] = t3;
            MMA4(dq[0], aq, B0);
            MMA4(dq[1], aq, B1);
        }
        // q[n] = row0 + row1 (lanes g=0 hold row0, g=1 row1)
        float r00 = dq[0][0] + __shfl_xor_sync(0xffffffffu, dq[0][0], 4);
        float r01 = dq[0][1] + __shfl_xor_sync(0xffffffffu, dq[0][1], 4);
        float r10 = dq[1][0] + __shfl_xor_sync(0xffffffffu, dq[1][0], 4);
        float r11 = dq[1][1] + __shfl_xor_sync(0xffffffffu, dq[1][1], 4);
        if (lane < 4) {
            int t = lane;
            q_s[wid * 16 + 2 * t]     = r00;
            q_s[wid * 16 + 2 * t + 1] = r01;
            q_s[wid * 16 + 8 + 2 * t]     = r10;
            q_s[wid * 16 + 8 + 2 * t + 1] = r11;
        }
    }
    __syncthreads();

    // -------- softmax over 64 (exact fp32; bias dropped: invariant) ---------
    if (tid < 32) {
        float m = fmaxf(q_s[tid], q_s[tid + 32]);
        #pragma unroll
        for (int o = 16; o > 0; o >>= 1)
            m = fmaxf(m, __shfl_xor_sync(0xffffffffu, m, o));
        if (tid == 0) red[0] = m;
    }
    __syncthreads();
    if (tid < 64) q_s[tid] = __expf(q_s[tid] - red[0]);
    __syncthreads();
    if (tid < 32) {
        float s = q_s[tid] + q_s[tid + 32];
        #pragma unroll
        for (int o = 16; o > 0; o >>= 1) s += __shfl_xor_sync(0xffffffffu, s, o);
        if (tid == 0) red[1] = 1.0f / s;
    }
    __syncthreads();
    if (tid < 64) {
        float s = q_s[tid] * red[1];
        float sh = h_hi(s);
        sp[tid] = __halves2half2(__float2half_rn(s), __float2half_rn(s - sh));
    }
    __syncthreads();

    // -------- xs = X.s via MMA (A = X non-trans ldmatrix; B = {s_hi,s_lo}) --
    {
        const int g = lane >> 2, t = lane & 3;
        float dx[2][4];
        #pragma unroll
        for (int i = 0; i < 2; i++)
            #pragma unroll
            for (int k = 0; k < 4; k++) dx[i][k] = 0.f;
        #pragma unroll
        for (int ks = 0; ks < 4; ks++) {
            __half2 pA = sp[ks * 16 + 2 * t];
            __half2 pB = sp[ks * 16 + 2 * t + 1];
            __half2 pC = sp[ks * 16 + 8 + 2 * t];
            __half2 pD = sp[ks * 16 + 9 + 2 * t];
            uint32_t B[2];
            B[0] = (g == 0) ? pack_hh(__low2half(pA), __low2half(pB))
                 : (g == 1) ? pack_hh(__high2half(pA), __high2half(pB)) : 0u;
            B[1] = (g == 0) ? pack_hh(__low2half(pC), __low2half(pD))
                 : (g == 1) ? pack_hh(__high2half(pC), __high2half(pD)) : 0u;
            #pragma unroll
            for (int mf = 0; mf < 2; mf++) {
                uint32_t aoff = (uint32_t)(wid * 32 + mf * 16 + lrow) * 144
                                + (ks * 16 + lcol) * 2;
                uint4 A;
                LDM4(A.x, A.y, A.z, A.w, smb + OFF_XH + aoff);
                MMA4(dx[mf], A, B);
                LDM4(A.x, A.y, A.z, A.w, smb + OFF_SCR + aoff);
                MMA4(dx[mf], A, B);
            }
        }
        if (t == 0) {                          // cols 0,1 -> xs = hi + lo parts
            #pragma unroll
            for (int mf = 0; mf < 2; mf++) {
                float x0 = dx[mf][0] + dx[mf][1];          // row g
                float x1 = dx[mf][2] + dx[mf][3];          // row g+8
                int r = wid * 32 + mf * 16 + g;
                float h0 = h_hi(x0), h1 = h_hi(x1);
                uint4 row;
                row.x = pack2h(h0, x0 - h0); row.y = 0u; row.z = 0u; row.w = 0u;
                *(uint4*)(smc + OFF_BX + (uint32_t)r * 16) = row;
                row.x = pack2h(h1, x1 - h1);
                *(uint4*)(smc + OFF_BX + (uint32_t)(r + 8) * 16) = row;
            }
        }
    }
    __syncthreads();

    // -------- cv = (Wk_hi + Wk_lo) . (xs_hi + xs_lo) via MMA ----------------
    {
        uint32_t bfr[16][2];
        #pragma unroll
        for (int c32 = 0; c32 < 8; c32++) {
            uint32_t t0, t1, t2, t3;
            LDM4T(t0, t1, t2, t3,
                  smb + OFF_BX + (uint32_t)(c32 * 32 + lane) * 16);
            bfr[2 * c32][0] = t0;     bfr[2 * c32][1] = t1;
            bfr[2 * c32 + 1][0] = t2; bfr[2 * c32 + 1][1] = t3;
        }
        float cva[2][4];
        #pragma unroll
        for (int mf = 0; mf < 2; mf++)
            #pragma unroll
            for (int k = 0; k < 4; k++) cva[mf][k] = 0.f;
        #pragma unroll
        for (int ks = 0; ks < 16; ks++) {
            #pragma unroll
            for (int mf = 0; mf < 2; mf++) {
                uint4 ah = __ldg(&sc_WF[2][ks][wid * 2 + mf][lane]);
                uint4 al = __ldg(&sc_WF[3][ks][wid * 2 + mf][lane]);
                MMA4(cva[mf], ah, bfr[ks]);
                MMA4(cva[mf], al, bfr[ks]);
            }
        }
        if ((lane & 3) == 0) {
            int g = lane >> 2;
            #pragma unroll
            for (int mf = 0; mf < 2; mf++) {
                int r = wid * 32 + mf * 16 + g;
                cv_s[r]     = cva[mf][0] + cva[mf][1] + __ldg(&bqkv[1 + r]);
                cv_s[r + 8] = cva[mf][2] + cva[mf][3] + __ldg(&bqkv[9 + r]);
            }
        }
    }
    // cv_s visibility for epi1 covered by post-GEMM1 __syncthreads.

    float acc[2][8][4];
    #pragma unroll
    for (int i = 0; i < 2; i++)
        #pragma unroll
        for (int j = 0; j < 8; j++)
            #pragma unroll
            for (int k = 0; k < 4; k++) acc[i][j][k] = 0.f;

    // ================= GEMM1: V = Wv . X =================
    gemm_main(&sc_WF[0][0][0][0], smb, acc, tid);

    __syncthreads();            // all B reads done before overwriting Xh
    {   // epi1: g = relu(v+bv)*cv -> Xh
        const int rb = wid * 32 + (lane >> 2);
        const int cb = 2 * (lane & 3);
        #pragma unroll
        for (int mf = 0; mf < 2; mf++)
            #pragma unroll
            for (int hf = 0; hf < 2; hf++) {
                int r = rb + 16 * mf + 8 * hf;
                float bv = __ldg(&bqkv[257 + r]);
                float cv = cv_s[r];
                #pragma unroll
                for (int nf = 0; nf < 8; nf++) {
                    float g0 = fmaxf(acc[mf][nf][2 * hf + 0] + bv, 0.f) * cv;
                    float g1 = fmaxf(acc[mf][nf][2 * hf + 1] + bv, 0.f) * cv;
                    uint32_t off = ((uint32_t)r * 72 + 8 * nf + cb) * 2;
                    *(uint32_t*)(smc + OFF_XH + off) = pack2h(g0, g1);
                }
            }
    }
    __syncthreads();            // G tile visible to all warps

    #pragma unroll
    for (int i = 0; i < 2; i++)
        #pragma unroll
        for (int j = 0; j < 8; j++)
            #pragma unroll
            for (int k = 0; k < 4; k++) acc[i][j][k] = 0.f;

    // ================= GEMM2: OUT = Wout . G =================
    gemm_main(&sc_WF[1][0][0][0], smb, acc, tid);

    {   // epi2: + bout -> global out
        float* ob = out + (size_t)b * 1048576 + (size_t)h * 64;
        const int rb = wid * 32 + (lane >> 2);
        const int cb = 2 * (lane & 3);
        #pragma unroll
        for (int mf = 0; mf < 2; mf++)
            #pragma unroll
            for (int hf = 0; hf < 2; hf++) {
                int r = rb + 16 * mf + 8 * hf;
                float bo = __ldg(&bout[r]);
                #pragma unroll
                for (int nf = 0; nf < 8; nf++) {
                    float2 v;
                    v.x = acc[mf][nf][2 * hf + 0] + bo;
                    v.y = acc[mf][nf][2 * hf + 1] + bo;
                    *(float2*)(ob + (size_t)r * 4096 + 8 * nf + cb) = v;
                }
            }
    }
}

// ============================================================================
extern "C" void kernel_launch(void* const* d_in, const int* in_sizes, int n_in,
                              void* d_out, int out_size)
{
    const float* x    = (const float*)d_in[0];
    const float* Wqkv = (const float*)d_in[1];
    const float* bqkv = (const float*)d_in[2];
    const float* Wout = (const float*)d_in[3];
    const float* bout = (const float*)d_in[4];
    float* out = (float*)d_out;

    cudaFuncSetAttribute(sepattn_tc,
                         cudaFuncAttributeMaxDynamicSharedMemorySize, SMEM_BYTES);
    prep_kernel<<<130, 256>>>(Wqkv, Wout);
    sepattn_tc<<<2048, 256, SMEM_BYTES>>>(x, Wqkv, bqkv, bout, out);
}